// round 4
// baseline (speedup 1.0000x reference)
#include <cuda_runtime.h>
#include <math.h>

#define EMAX 4096
#define CAP (EMAX*(EMAX-1)/2)
#define NBLK 128
#define NTHR 512
#define NTOT (NBLK*NTHR)      // 65536
#define NWARPS (NTOT/32)      // 2048

// ---- device scratch (no allocations allowed) ----
__device__ float g_ang[EMAX];
__device__ float g_nx[EMAX], g_ny[EMAX], g_c[EMAX], g_mx[EMAX], g_my[EMAX];
__device__ float g_sang[EMAX];
__device__ unsigned short g_sidx[EMAX];
__device__ unsigned int g_count;
__device__ float g_buf[CAP];
__device__ unsigned int g_hist16[65536];      // top-16-bit bins (pass 1)
__device__ unsigned int g_hist16b[3*65536];   // low-16-bit bins per rank (pass 2)
__device__ unsigned int g_part1[NBLK];        // cross-block partials, pass 1
__device__ unsigned int g_part3[3*NBLK];      // cross-block partials, pass 2
__device__ unsigned int g_pfx16[3];
__device__ unsigned int g_rank[3];
__device__ float g_qval[3];
__device__ double g_sum;
// persistent-safe grid barrier state (monotone, never reset)
__device__ unsigned int g_sense_v;
__device__ unsigned int g_arrive_v;

#define PI_F  3.14159274101257324f
#define THR_F 0.08726646259971647f

// ---------------------------------------------------------------------------
// Grid barrier: cumulative arrive counter + monotone sense. Barrier T
// completes when arrivals == T*NBLK (mod 2^32). Safe across graph replays:
// no barrier completes until every block arrives, so a block's entry read of
// g_sense_v always sees the launch base.
// ---------------------------------------------------------------------------
__device__ __forceinline__ void grid_sync(unsigned base, unsigned& bidx)
{
    __syncthreads();
    if (threadIdx.x == 0) {
        unsigned target = base + (++bidx);
        __threadfence();
        unsigned old = atomicAdd(&g_arrive_v, 1u);
        if (old + 1u == target * NBLK) {
            __threadfence();
            *(volatile unsigned*)&g_sense_v = target;
        } else {
            while ((int)(*(volatile unsigned*)&g_sense_v - target) < 0)
                __nanosleep(32);
        }
        __threadfence();
    }
    __syncthreads();
}

// 512-thread Hillis-Steele inclusive scan in shared. Returns inclusive value.
__device__ __forceinline__ unsigned block_scan(unsigned* sh, unsigned v)
{
    int t = threadIdx.x;
    sh[t] = v;
    __syncthreads();
    #pragma unroll
    for (int off = 1; off < NTHR; off <<= 1) {
        unsigned x = sh[t];
        unsigned a = (t >= off) ? sh[t - off] : 0u;
        __syncthreads();
        sh[t] = x + a;
        __syncthreads();
    }
    return sh[t];
}

__device__ __forceinline__ void emit_warp(bool in, float dist, int lane)
{
    const unsigned FULL = 0xFFFFFFFFu;
    unsigned ball = __ballot_sync(FULL, in);
    if (ball) {
        int leader = __ffs(ball) - 1;
        unsigned base = 0;
        if (lane == leader) base = atomicAdd(&g_count, (unsigned)__popc(ball));
        base = __shfl_sync(FULL, base, leader);
        if (in) {
            g_buf[base + __popc(ball & ((1u << lane) - 1u))] = dist;
            atomicAdd(&g_hist16[__float_as_uint(dist) >> 16], 1u);  // pass-1 hist
        }
    }
}

// ---------------------------------------------------------------------------
__global__ void __launch_bounds__(NTHR, 1)
k_all(const float* __restrict__ pos, const int* __restrict__ eidx,
      float* __restrict__ out, int E)
{
    __shared__ float          sh_f[EMAX];      // sort keys (block 0)
    __shared__ unsigned short sh_i[EMAX];      // sort payload
    __shared__ unsigned       sh_scan[NTHR];
    __shared__ unsigned       sh_part[NBLK + 1];
    __shared__ unsigned       sh_sense;

    const int tid  = threadIdx.x;
    const int bid  = blockIdx.x;
    const int gtid = bid * NTHR + tid;

    if (tid == 0) sh_sense = *(volatile unsigned*)&g_sense_v;
    __syncthreads();
    const unsigned base = sh_sense;
    unsigned bidx = 0;

    // ---------------- P0: zero scratch + per-edge geometry ----------------
    if (gtid == 0) { g_count = 0u; g_sum = 0.0; }
    g_hist16[gtid] = 0u;
    #pragma unroll
    for (int k = 0; k < 3; k++) g_hist16b[k * 65536 + gtid] = 0u;

    if (gtid < E) {
        int e = gtid;
        int s = eidx[e];
        int d = eidx[E + e];
        float sx = pos[2*s], sy = pos[2*s+1];
        float dx = pos[2*d], dy = pos[2*d+1];
        float vx = dx - sx, vy = dy - sy;
        float len = fmaxf(sqrtf(vx*vx + vy*vy), 1e-8f);
        float ux = vx / len, uy = vy / len;
        float a = atan2f(uy, ux);
        a = fmodf(a, PI_F);
        if (a < 0.f) a += PI_F;
        g_ang[e] = a;
        float nx = -uy, ny = ux;
        g_nx[e] = nx;  g_ny[e] = ny;
        g_c[e]  = sx*nx + sy*ny;
        g_mx[e] = (sx + dx) * 0.5f;
        g_my[e] = (sy + dy) * 0.5f;
    }
    grid_sync(base, bidx);                                           // B1

    // ---------------- P1: bitonic sort of (angle, idx) in block 0 ---------
    if (bid == 0) {
        for (int t = tid; t < EMAX; t += NTHR) {
            sh_f[t] = (t < E) ? g_ang[t] : 3.4e38f;
            sh_i[t] = (unsigned short)t;
        }
        __syncthreads();
        for (int k = 2; k <= EMAX; k <<= 1) {
            for (int j = k >> 1; j > 0; j >>= 1) {
                for (int t = tid; t < EMAX; t += NTHR) {
                    int p = t ^ j;
                    if (p > t) {
                        bool up = ((t & k) == 0);
                        float va = sh_f[t], vb = sh_f[p];
                        if ((va > vb) == up) {
                            sh_f[t] = vb; sh_f[p] = va;
                            unsigned short ia = sh_i[t]; sh_i[t] = sh_i[p]; sh_i[p] = ia;
                        }
                    }
                }
                __syncthreads();
            }
        }
        for (int t = tid; t < EMAX; t += NTHR) {
            g_sang[t] = sh_f[t];
            g_sidx[t] = sh_i[t];
        }
    }
    grid_sync(base, bidx);                                           // B2

    // ---------------- P2: sorted pair sweep (1 warp per i, strided) -------
    {
        const int gwarp = gtid >> 5;
        const int lane  = gtid & 31;
        for (int i = gwarp; i < E - 1; i += NWARPS) {
            float ai = g_sang[i];
            int   oi = g_sidx[i];
            // forward prefix: da <= THR (monotone in sorted order)
            for (int jb = i + 1; jb < E; jb += 32) {
                int  j   = jb + lane;
                bool in  = false;
                float dist = 0.f;
                if (j < E) {
                    float da = fabsf(ai - g_sang[j]);
                    if (da <= THR_F) {
                        in = true;
                        int oj = (int)g_sidx[j];
                        int a = min(oi, oj), b = max(oi, oj);
                        dist = fabsf(fmaf(g_nx[a], g_mx[b], fmaf(g_ny[a], g_my[b], -g_c[a])));
                    }
                }
                emit_warp(in, dist, lane);
                if (__any_sync(0xFFFFFFFFu, !in)) break;
            }
            // wraparound suffix: da > THR && PI-da <= THR
            for (int jb = E - 1; jb > i; jb -= 32) {
                int  j    = jb - lane;
                bool in   = false;
                bool stop = true;
                float dist = 0.f;
                if (j > i) {
                    float da = fabsf(ai - g_sang[j]);
                    stop = ((PI_F - da) > THR_F);
                    if (!stop && da > THR_F) {
                        in = true;
                        int oj = (int)g_sidx[j];
                        int a = min(oi, oj), b = max(oi, oj);
                        dist = fabsf(fmaf(g_nx[a], g_mx[b], fmaf(g_ny[a], g_my[b], -g_c[a])));
                    }
                }
                emit_warp(in, dist, lane);
                if (__any_sync(0xFFFFFFFFu, stop)) break;
            }
        }
    }
    grid_sync(base, bidx);                                           // B3

    // ---------------- P3: selection pass 1 (1 bin per thread) -------------
    unsigned h1  = g_hist16[gtid];
    unsigned inc1 = block_scan(sh_scan, h1);
    unsigned exc1 = inc1 - h1;
    if (tid == NTHR - 1) g_part1[bid] = inc1;
    grid_sync(base, bidx);                                           // B4

    unsigned n = g_count;
    {
        // cross-block exclusive base (serial 128-scan in shared; cheap)
        if (tid < NBLK) sh_part[tid] = g_part1[tid];
        __syncthreads();
        if (tid == 0) {
            unsigned acc = 0;
            for (int b = 0; b < NBLK; b++) { unsigned v = sh_part[b]; sh_part[b] = acc; acc += v; }
        }
        __syncthreads();
        unsigned excg = sh_part[bid] + exc1;

        int r0 = (int)(n/4) - 1; if (r0 < 0) r0 = 0;
        int r1 = (int)(n/2);
        int r2 = (int)((3*(long long)n)/4); if (r2 > (int)n - 1) r2 = (int)n - 1;
        if (r2 < 0) r2 = 0;
        unsigned rr[3] = {(unsigned)r0, (unsigned)r1, (unsigned)r2};
        #pragma unroll
        for (int s = 0; s < 3; s++) {
            unsigned r = rr[s];
            if (h1 && excg <= r && r < excg + h1) {
                g_pfx16[s] = (unsigned)gtid;
                g_rank[s]  = r - excg;
            }
        }
    }
    grid_sync(base, bidx);                                           // B5

    // ---------------- P4: pass-2 histogram over g_buf ---------------------
    {
        unsigned p0 = g_pfx16[0], p1 = g_pfx16[1], p2 = g_pfx16[2];
        for (unsigned idx = gtid; idx < n; idx += NTOT) {
            unsigned bits = __float_as_uint(g_buf[idx]);
            unsigned hi = bits >> 16, lo = bits & 0xFFFFu;
            if (hi == p0) atomicAdd(&g_hist16b[lo],          1u);
            if (hi == p1) atomicAdd(&g_hist16b[65536  + lo], 1u);
            if (hi == p2) atomicAdd(&g_hist16b[131072 + lo], 1u);
        }
    }
    grid_sync(base, bidx);                                           // B6

    // ---------------- P5: selection pass 2 (3 ranks) ----------------------
    unsigned h2[3], exc2[3];
    #pragma unroll
    for (int s = 0; s < 3; s++) {
        unsigned h   = g_hist16b[s * 65536 + gtid];
        unsigned inc = block_scan(sh_scan, h);
        h2[s]  = h;
        exc2[s] = inc - h;
        if (tid == NTHR - 1) g_part3[s * NBLK + bid] = inc;
    }
    grid_sync(base, bidx);                                           // B7

    #pragma unroll
    for (int s = 0; s < 3; s++) {
        if (tid < NBLK) sh_part[tid] = g_part3[s * NBLK + tid];
        __syncthreads();
        if (tid == 0) {
            unsigned acc = 0;
            for (int b = 0; b < NBLK; b++) { unsigned v = sh_part[b]; sh_part[b] = acc; acc += v; }
        }
        __syncthreads();
        unsigned excg = sh_part[bid] + exc2[s];
        unsigned r = g_rank[s];
        if (h2[s] && excg <= r && r < excg + h2[s])
            g_qval[s] = __uint_as_float((g_pfx16[s] << 16) | (unsigned)gtid);
        __syncthreads();
    }
    grid_sync(base, bidx);                                           // B8

    // ---------------- P6: hinge-loss sum + finalize -----------------------
    {
        float q1 = g_qval[0], mu = g_qval[1], q3 = g_qval[2];
        float margin = fmaxf(q3 - q1, 1e-6f) * 0.75f;   // iqr * 0.5 * 1.5

        double local = 0.0;
        for (unsigned idx = gtid; idx < n; idx += NTOT) {
            float d = g_buf[idx];
            float v = fabsf(d - mu) - margin;
            if (v > 0.f) local += (double)v;
        }
        for (int o = 16; o; o >>= 1) local += __shfl_down_sync(0xFFFFFFFFu, local, o);
        __shared__ double shs[NTHR/32];
        if ((tid & 31) == 0) shs[tid >> 5] = local;
        __syncthreads();
        if (tid < 32) {
            double v = (tid < NTHR/32) ? shs[tid] : 0.0;
            for (int o = 16; o; o >>= 1) v += __shfl_down_sync(0xFFFFFFFFu, v, o);
            if (tid == 0 && v != 0.0) atomicAdd(&g_sum, v);
        }
    }
    grid_sync(base, bidx);                                           // B9

    if (gtid == 0) {
        double denom = (double)(n > 0u ? n : 1u);
        out[0] = (float)(*(volatile double*)&g_sum / denom);
    }
}

// ---------------------------------------------------------------------------
extern "C" void kernel_launch(void* const* d_in, const int* in_sizes, int n_in,
                              void* d_out, int out_size)
{
    const float* pos  = (const float*)d_in[0];   // node_positions (B*N, 2)
    // d_in[1] = adjacency: unused
    const int*   eidx = (const int*)d_in[2];     // edge_index (2, E)
    float* out = (float*)d_out;

    int E = in_sizes[2] / 2;
    if (E > EMAX) E = EMAX;

    k_all<<<NBLK, NTHR>>>(pos, eidx, out, E);
}